// round 7
// baseline (speedup 1.0000x reference)
#include <cuda_runtime.h>

// Analytic collapse of SpatialAttentionLayer:
// V = ones(B,L,O,d)  =>
//   relu(V@Wk+bk) = rk[d] = relu(colsum(Wk)[d] + bk[d]), constant over (b,l,o)
//   _attention_net rows constant along softmax axis => phi=psi=theta=1/O,
//   and (uniform) @ rk-rows = rk.
// => M[b,l,o,d] = r1[d]+r2[d]+r3[d]+r4[d], broadcast to [8,12,64,128].
//
// Single fused launch: each block redundantly computes r[128] (256 KB of
// weight reads, L2-resident), then writes its slice of the 3 MB output.
// Rationale: at this size each kernel launch costs ~3-4 us wall; two
// launches dominated R5/R6. One launch + ~1.5 us of work beats that.

#define D  128
#define NB 32
#define NT 1024

__global__ void __launch_bounds__(NT, 1)
fused_kernel(const float* __restrict__ W1, const float* __restrict__ b1,
             const float* __restrict__ W2, const float* __restrict__ b2,
             const float* __restrict__ W3, const float* __restrict__ b3,
             const float* __restrict__ W4, const float* __restrict__ b4,
             float4* __restrict__ out, int n4) {
    __shared__ float part[4][2][D];
    __shared__ float rvec[D];

    const int tid = threadIdx.x;
    // 1024 threads = 4 matrices x 2 row-halves x 128 columns
    const int k = tid >> 8;          // 0..3  which weight matrix
    const int t = tid & 255;
    const int q = t >> 7;            // 0..1  which 64-row half
    const int d = t & (D - 1);       // 0..127 column

    const float* __restrict__ W = (k == 0) ? W1 : (k == 1) ? W2 : (k == 2) ? W3 : W4;
    const float* __restrict__ p = W + (q * 64) * D + d;

    float s0 = 0.f, s1 = 0.f, s2 = 0.f, s3 = 0.f;
#pragma unroll
    for (int i = 0; i < 64; i += 4) {        // coalesced across the 128 d-threads
        s0 += p[(i + 0) * D];
        s1 += p[(i + 1) * D];
        s2 += p[(i + 2) * D];
        s3 += p[(i + 3) * D];
    }
    part[k][q][d] = (s0 + s1) + (s2 + s3);
    __syncthreads();

    if (tid < D) {
        float acc =
              fmaxf(b1[tid] + part[0][0][tid] + part[0][1][tid], 0.f)
            + fmaxf(b2[tid] + part[1][0][tid] + part[1][1][tid], 0.f)
            + fmaxf(b3[tid] + part[2][0][tid] + part[2][1][tid], 0.f)
            + fmaxf(b4[tid] + part[3][0][tid] + part[3][1][tid], 0.f);
        rvec[tid] = acc;
    }
    __syncthreads();

    // Output float4 index i covers d = 4*(i&31) .. 4*(i&31)+3.
    // NT and the grid stride are multiples of 32, so (i & 31) == (tid & 31)
    // for every iteration: one register-resident float4 per thread.
    const float4 v = reinterpret_cast<const float4*>(rvec)[tid & 31];
    const int stride = NB * NT;              // 32768, multiple of 32
    for (int i = blockIdx.x * NT + tid; i < n4; i += stride) {
        out[i] = v;                          // 196608/32768 = 6 exact iters
    }
}

extern "C" void kernel_launch(void* const* d_in, const int* in_sizes, int n_in,
                              void* d_out, int out_size) {
    // metadata order: X(0), a{W1,b1,W2,b2,w3,b3}(1..6), b{...}(7..12),
    // c{...}(13..18), W1(19),b1(20),W2(21),b2(22),W3(23),b3(24),W4(25),b4(26)
    const float* W1 = (const float*)d_in[19];
    const float* b1 = (const float*)d_in[20];
    const float* W2 = (const float*)d_in[21];
    const float* b2 = (const float*)d_in[22];
    const float* W3 = (const float*)d_in[23];
    const float* b3 = (const float*)d_in[24];
    const float* W4 = (const float*)d_in[25];
    const float* b4 = (const float*)d_in[26];

    const int n4 = out_size / 4;  // 196608 float4 stores
    fused_kernel<<<NB, NT>>>(W1, b1, W2, b2, W3, b3, W4, b4, (float4*)d_out, n4);
}

// round 8
// speedup vs baseline: 1.3140x; 1.3140x over previous
#include <cuda_runtime.h>

// Analytic collapse of SpatialAttentionLayer:
// V = ones(B,L,O,d)  =>
//   relu(V@Wk+bk) = rk[d] = relu(colsum(Wk)[d] + bk[d]), constant over (b,l,o)
//   _attention_net rows constant along softmax axis => phi=psi=theta=1/O,
//   and (uniform) @ rk-rows = rk.
// => M[b,l,o,d] = Σ_k relu(colsum(Wk)[d]+bk[d]), broadcast to [8,12,64,128].
//
// R7: partition by COLUMN GROUP to kill redundant weight reads.
// r[c] is per-column independent, so a block that writes only columns
// [32g, 32g+32) needs just those 32 columns of each W: 64 KB (512 L1
// wavefronts) instead of 256 KB (2048). 32 floats = 128 B = one full cache
// line, so stores remain full-line. Grid = 4 col-groups x 16 row-splits.

#define D      128
#define NROWS  6144          // 8*12*64 output rows
#define GSPLIT 4             // column groups of 32
#define RSPLIT 16            // row splits of 384
#define NT     512           // 16 warps

__global__ void __launch_bounds__(NT, 1)
fused_kernel(const float* __restrict__ W1, const float* __restrict__ b1,
             const float* __restrict__ W2, const float* __restrict__ b2,
             const float* __restrict__ W3, const float* __restrict__ b3,
             const float* __restrict__ W4, const float* __restrict__ b4,
             float4* __restrict__ out) {
    __shared__ float part[16][32];
    __shared__ float rvec[32];

    const int tid  = threadIdx.x;
    const int w    = tid >> 5;           // warp 0..15
    const int lane = tid & 31;
    const int g    = blockIdx.x & (GSPLIT - 1);   // column group
    const int s    = blockIdx.x >> 2;             // row split
    const int c0   = g * 32;                      // first column of group

    // ---- Phase 1: partial column sums for this 32-column group ----
    // warp w: matrix m = w>>2, row chunk = w&3 (rows [32*chunk, 32*chunk+32))
    {
        const int m     = w >> 2;
        const int chunk = w & 3;
        const float* __restrict__ W =
            (m == 0) ? W1 : (m == 1) ? W2 : (m == 2) ? W3 : W4;
        const float* __restrict__ p = W + (chunk * 32) * D + c0 + lane;
        float s0 = 0.f, s1 = 0.f, s2 = 0.f, s3 = 0.f;
#pragma unroll
        for (int i = 0; i < 32; i += 4) {   // coalesced: warp covers one 128B line
            s0 += p[(i + 0) * D];
            s1 += p[(i + 1) * D];
            s2 += p[(i + 2) * D];
            s3 += p[(i + 3) * D];
        }
        part[w][lane] = (s0 + s1) + (s2 + s3);
    }
    __syncthreads();

    // ---- Combine: r[c] = Σ_m relu(b_m[c] + colsum_m[c]) for c in group ----
    if (tid < 32) {
        const int c = c0 + tid;
        float acc =
              fmaxf(b1[c] + ((part[ 0][tid] + part[ 1][tid]) + (part[ 2][tid] + part[ 3][tid])), 0.f)
            + fmaxf(b2[c] + ((part[ 4][tid] + part[ 5][tid]) + (part[ 6][tid] + part[ 7][tid])), 0.f)
            + fmaxf(b3[c] + ((part[ 8][tid] + part[ 9][tid]) + (part[10][tid] + part[11][tid])), 0.f)
            + fmaxf(b4[c] + ((part[12][tid] + part[13][tid]) + (part[14][tid] + part[15][tid])), 0.f);
        rvec[tid] = acc;
    }
    __syncthreads();

    // ---- Phase 2: broadcast-store 128B per row for 384 rows ----
    // lane = (rsub: 2 bits row-within-quad-of-rows, q: 3 bits float4 index)
    // each warp stores 4 rows x 128B per STG.128 wave; 6 iterations = 24 rows.
    const int q    = lane & 7;            // float4 index within 128B group
    const int rsub = lane >> 3;           // 0..3
    const float4 v = reinterpret_cast<const float4*>(rvec)[q];

    const int row0 = s * (NROWS / RSPLIT) + w * 24 + rsub;   // + it*4
    float4* __restrict__ o = out + (long)row0 * 32 + g * 8 + q;
#pragma unroll
    for (int it = 0; it < 6; ++it) {
        o[(long)it * 4 * 32] = v;         // rows stride 4, each row = 32 float4
    }
}

extern "C" void kernel_launch(void* const* d_in, const int* in_sizes, int n_in,
                              void* d_out, int out_size) {
    // metadata order: X(0), a{W1,b1,W2,b2,w3,b3}(1..6), b{...}(7..12),
    // c{...}(13..18), W1(19),b1(20),W2(21),b2(22),W3(23),b3(24),W4(25),b4(26)
    const float* W1 = (const float*)d_in[19];
    const float* b1 = (const float*)d_in[20];
    const float* W2 = (const float*)d_in[21];
    const float* b2 = (const float*)d_in[22];
    const float* W3 = (const float*)d_in[23];
    const float* b3 = (const float*)d_in[24];
    const float* W4 = (const float*)d_in[25];
    const float* b4 = (const float*)d_in[26];

    fused_kernel<<<GSPLIT * RSPLIT, NT>>>(W1, b1, W2, b2, W3, b3, W4, b4,
                                          (float4*)d_out);
}